// round 5
// baseline (speedup 1.0000x reference)
#include <cuda_runtime.h>
#include <cuda_bf16.h>
#include <cstdint>

#define N_IMG 16
#define C_IN  256
#define HW    128
#define C_OUT 128
#define HALO  130

// e4m3 encodings of {+1, -1, 0}
#define FP8_P1 0x38u
#define FP8_M1 0xB8u

// Scratch (module-load allocated; zero-initialized => halo stays zero forever)
__device__ __align__(1024) uint8_t g_xb[(size_t)N_IMG * HALO * HALO * C_IN];  // sign(x) NHWC e4m3
__device__ __align__(16)   uint2  g_wfrag[36 * 2 * 16 * 32];  // [chunk][kt][ntile][lane] e4m3 B-frags
__device__ float g_alpha[C_OUT];

__device__ __forceinline__ float sgnf(float v) {
    return (v > 0.f) ? 1.f : ((v < 0.f) ? -1.f : 0.f);
}
__device__ __forceinline__ uint8_t sgn_fp8(float v) {
    return (v > 0.f) ? (uint8_t)FP8_P1 : ((v < 0.f) ? (uint8_t)FP8_M1 : (uint8_t)0);
}

// ---------------------------------------------------------------------------
// Kernel 1: sign(x) NCHW f32 -> NHWC e4m3 with +1 halo offset (zero padding)
// ---------------------------------------------------------------------------
__global__ void pack_x_kernel(const float* __restrict__ x) {
    __shared__ float tile[32][33];
    int nh = blockIdx.z;              // n*128 + h
    int n = nh >> 7, h = nh & 127;
    int wt = blockIdx.y;              // 0..3  (w tile of 32)
    int ct = blockIdx.x;              // 0..7  (c tile of 32)
    int tx = threadIdx.x, ty = threadIdx.y;

#pragma unroll
    for (int j = 0; j < 4; j++) {
        int cl = ty + j * 8;
        float v = x[(((size_t)(n * C_IN + ct * 32 + cl)) * HW + h) * HW + wt * 32 + tx];
        tile[cl][tx] = sgnf(v);
    }
    __syncthreads();
#pragma unroll
    for (int j = 0; j < 4; j++) {
        int wl = ty + j * 8;
        size_t dst = (((size_t)n * HALO + (h + 1)) * HALO + (wt * 32 + wl + 1)) * C_IN
                   + ct * 32 + tx;
        g_xb[dst] = sgn_fp8(tile[tx][wl]);
    }
}

// ---------------------------------------------------------------------------
// Kernel 2: sign(W) OIHW -> mma.m16n8k32 e4m3 B-fragment order
// B frag (32x8 col-major): lane -> col lane/4; b0 = k (lane%4)*4+{0..3}, b1 = +16
// chunk = (ky,kx,cc): ky=chunk/12, kx=(chunk/4)%3, cc=chunk&3 (cc = 64-ci slice)
// ---------------------------------------------------------------------------
__global__ void pack_w_kernel(const float* __restrict__ w) {
    int g = blockIdx.x * 256 + threadIdx.x;   // 36*2*16*32 = 36864
    int lane  = g & 31;
    int nt    = (g >> 5) & 15;   // n-tile (8 couts)
    int kt    = (g >> 9) & 1;    // k-tile (32 ci) within 64-chunk
    int chunk = g >> 10;         // 0..35
    int ky = chunk / 12, kx = (chunk / 4) % 3, cc = chunk & 3;

    int ci0 = cc * 64 + kt * 32 + (lane & 3) * 4;
    int co  = nt * 8 + (lane >> 2);

    auto widx = [&](int ci) { return (((size_t)co * C_IN + ci) * 3 + ky) * 3 + kx; };
    uint32_t lo = 0, hi = 0;
#pragma unroll
    for (int j = 0; j < 4; j++) {
        lo |= ((uint32_t)sgn_fp8(w[widx(ci0 + j)]))      << (8 * j);
        hi |= ((uint32_t)sgn_fp8(w[widx(ci0 + 16 + j)])) << (8 * j);
    }
    g_wfrag[g] = make_uint2(lo, hi);
}

// ---------------------------------------------------------------------------
// Kernel 3: alpha[co] = mean |W[co,:,:,:]|
// ---------------------------------------------------------------------------
__global__ void alpha_kernel(const float* __restrict__ w) {
    __shared__ float red[256];
    int co = blockIdx.x;
    float s = 0.f;
    for (int i = threadIdx.x; i < 2304; i += 256)
        s += fabsf(w[(size_t)co * 2304 + i]);
    red[threadIdx.x] = s;
    __syncthreads();
    for (int o = 128; o > 0; o >>= 1) {
        if (threadIdx.x < o) red[threadIdx.x] += red[threadIdx.x + o];
        __syncthreads();
    }
    if (threadIdx.x == 0) g_alpha[co] = red[0] / 2304.f;
}

// ---------------------------------------------------------------------------
// Kernel 4: e4m3 implicit-GEMM conv. CTA = one output row (n,h):
//   M=128 pixels, N=128 couts, K = 36 chunks x 64 ci.
//   4-stage cp.async ring, ONE __syncthreads per chunk, 2 CTAs/SM.
// ---------------------------------------------------------------------------
#define A_STRIDE 80                    // 64 ci + 16B pad -> conflict-free ldmatrix
#define ASZ (128 * A_STRIDE)           // 10240
#define BSZ (2 * 16 * 32 * 8)          // 8192
#define STAGE (ASZ + BSZ)              // 18432
#define STAGES 4
#define SMEM_DYN (STAGES * STAGE)      // 73728

__device__ __forceinline__ void issue_loads(char* smem, int stage, int tid,
                                            int n, int h, int it) {
    int ky = it / 12, kx = (it / 4) % 3, cc = it & 3;
    char* sA = smem + stage * STAGE;
    char* sB = sA + ASZ;
    const uint8_t* gx = &g_xb[(((size_t)n * HALO + h + ky) * HALO + kx) * C_IN + cc * 64];
#pragma unroll
    for (int v = 0; v < 2; v++) {
        int u = tid + v * 256;            // 512 units of 16B for A
        int row = u >> 2, seg = u & 3;
        uint32_t sa = (uint32_t)__cvta_generic_to_shared(sA + row * A_STRIDE + seg * 16);
        const void* ga = gx + (size_t)row * C_IN + seg * 16;
        asm volatile("cp.async.cg.shared.global [%0], [%1], 16;\n" :: "r"(sa), "l"(ga));
    }
    const char* gw = ((const char*)g_wfrag) + (size_t)it * BSZ;
#pragma unroll
    for (int v = 0; v < 2; v++) {
        int u = tid + v * 256;            // 512 units of 16B for B
        uint32_t sa = (uint32_t)__cvta_generic_to_shared(sB + u * 16);
        asm volatile("cp.async.cg.shared.global [%0], [%1], 16;\n" :: "r"(sa), "l"(gw + u * 16));
    }
    asm volatile("cp.async.commit_group;\n");
}

__global__ void __launch_bounds__(256, 2) conv_kernel(float* __restrict__ out) {
    extern __shared__ char smem[];
    int tid = threadIdx.x;
    int lane = tid & 31, wid = tid >> 5;
    int wm = wid >> 2;        // 0..1 : 64-row M slab
    int wn = wid & 3;         // 0..3 : 32-col N slab
    int h = blockIdx.x, n = blockIdx.y;

    float acc[4][4][4];
#pragma unroll
    for (int a = 0; a < 4; a++)
#pragma unroll
        for (int b = 0; b < 4; b++)
#pragma unroll
            for (int c = 0; c < 4; c++) acc[a][b][c] = 0.f;

    issue_loads(smem, 0, tid, n, h, 0);
    issue_loads(smem, 1, tid, n, h, 1);
    issue_loads(smem, 2, tid, n, h, 2);

    int rl = lane & 15;             // ldmatrix row-within-16
    int cl = (lane >> 4) * 16;      // ldmatrix 16B-column half

    for (int it = 0; it < 36; it++) {
        asm volatile("cp.async.wait_group 2;\n");
        __syncthreads();

        const char*  sA = smem + (it & 3) * STAGE;
        const uint2* sB = (const uint2*)(sA + ASZ);

#pragma unroll
        for (int kt = 0; kt < 2; kt++) {
            uint32_t a[4][4];
#pragma unroll
            for (int mt = 0; mt < 4; mt++) {
                uint32_t addr = (uint32_t)__cvta_generic_to_shared(
                    sA + (wm * 64 + mt * 16 + rl) * A_STRIDE + kt * 32 + cl);
                asm volatile(
                    "ldmatrix.sync.aligned.m8n8.x4.shared.b16 {%0,%1,%2,%3}, [%4];"
                    : "=r"(a[mt][0]), "=r"(a[mt][1]), "=r"(a[mt][2]), "=r"(a[mt][3])
                    : "r"(addr));
            }
            uint32_t b[4][2];
#pragma unroll
            for (int nt = 0; nt < 4; nt++) {
                uint2 t = sB[(kt * 16 + wn * 4 + nt) * 32 + lane];
                b[nt][0] = t.x; b[nt][1] = t.y;
            }
#pragma unroll
            for (int mt = 0; mt < 4; mt++)
#pragma unroll
                for (int nt = 0; nt < 4; nt++)
                    asm volatile(
                        "mma.sync.aligned.m16n8k32.row.col.f32.e4m3.e4m3.f32 "
                        "{%0,%1,%2,%3}, {%4,%5,%6,%7}, {%8,%9}, {%0,%1,%2,%3};"
                        : "+f"(acc[mt][nt][0]), "+f"(acc[mt][nt][1]),
                          "+f"(acc[mt][nt][2]), "+f"(acc[mt][nt][3])
                        : "r"(a[mt][0]), "r"(a[mt][1]), "r"(a[mt][2]), "r"(a[mt][3]),
                          "r"(b[nt][0]), "r"(b[nt][1]));
        }

        if (it + 3 < 36)
            issue_loads(smem, (it + 3) & 3, tid, n, h, it + 3);
        else
            asm volatile("cp.async.commit_group;\n");   // keep wait_group accounting
    }

    // Epilogue: frags -> smem [co][w] (pad 132), then coalesced NCHW store * alpha[w]
    __syncthreads();
    float* so = (float*)smem;
#pragma unroll
    for (int mt = 0; mt < 4; mt++) {
        int r0 = wm * 64 + mt * 16 + (lane >> 2);   // w index
#pragma unroll
        for (int nt = 0; nt < 4; nt++) {
            int c0 = wn * 32 + nt * 8 + (lane & 3) * 2;   // co index
            so[(size_t)c0 * 132 + r0]           = acc[mt][nt][0];
            so[(size_t)(c0 + 1) * 132 + r0]     = acc[mt][nt][1];
            so[(size_t)c0 * 132 + r0 + 8]       = acc[mt][nt][2];
            so[(size_t)(c0 + 1) * 132 + r0 + 8] = acc[mt][nt][3];
        }
    }
    __syncthreads();

    int w = tid & 127;
    float al = g_alpha[w];
    float* ob = out + ((size_t)n * C_OUT * HW + (size_t)h) * HW;   // + co*HW*HW + w
#pragma unroll 4
    for (int k = 0; k < 64; k++) {
        int co = (tid >> 7) + k * 2;
        ob[(size_t)co * HW * HW + w] = so[(size_t)co * 132 + w] * al;
    }
}

// ---------------------------------------------------------------------------
extern "C" void kernel_launch(void* const* d_in, const int* in_sizes, int n_in,
                              void* d_out, int out_size) {
    (void)in_sizes; (void)n_in; (void)out_size;
    const float* x = (const float*)d_in[0];
    const float* w = (const float*)d_in[1];
    float* out = (float*)d_out;

    cudaFuncSetAttribute(conv_kernel,
                         cudaFuncAttributeMaxDynamicSharedMemorySize, SMEM_DYN);

    dim3 pg(8, 4, N_IMG * HW);
    dim3 pb(32, 8);
    pack_x_kernel<<<pg, pb>>>(x);
    pack_w_kernel<<<144, 256>>>(w);
    alpha_kernel<<<C_OUT, 256>>>(w);
    conv_kernel<<<dim3(HW, N_IMG), 256, SMEM_DYN>>>(out);
}

// round 6
// speedup vs baseline: 1.1027x; 1.1027x over previous
#include <cuda_runtime.h>
#include <cuda_bf16.h>
#include <cstdint>

#define N_IMG 16
#define C_IN  256
#define HW    128
#define C_OUT 128
#define HALO  130

// Scratch (module-load allocated; zero-initialized => halo stays zero forever)
__device__ __align__(1024) __nv_bfloat16 g_xb[(size_t)N_IMG * HALO * HALO * C_IN];
__device__ __align__(16) uint2 g_wfrag[36 * 4 * 16 * 32];   // [chunk][kt][ntile][lane]
__device__ float g_alpha[C_OUT];

__device__ __forceinline__ float sgnf(float v) {
    return (v > 0.f) ? 1.f : ((v < 0.f) ? -1.f : 0.f);
}
__device__ __forceinline__ uint16_t f2bf_bits(float v) {
    __nv_bfloat16 b = __float2bfloat16(v);
    return *reinterpret_cast<uint16_t*>(&b);
}

// ---------------------------------------------------------------------------
// Kernel 1: sign(x) NCHW f32 -> NHWC bf16 with +1 halo offset (zero padding)
// ---------------------------------------------------------------------------
__global__ void pack_x_kernel(const float* __restrict__ x) {
    __shared__ float tile[32][33];
    int nh = blockIdx.z;              // n*128 + h
    int n = nh >> 7, h = nh & 127;
    int wt = blockIdx.y;              // 0..3  (w tile of 32)
    int ct = blockIdx.x;              // 0..7  (c tile of 32)
    int tx = threadIdx.x, ty = threadIdx.y;

#pragma unroll
    for (int j = 0; j < 4; j++) {
        int cl = ty + j * 8;
        float v = x[(((size_t)(n * C_IN + ct * 32 + cl)) * HW + h) * HW + wt * 32 + tx];
        tile[cl][tx] = sgnf(v);
    }
    __syncthreads();
#pragma unroll
    for (int j = 0; j < 4; j++) {
        int wl = ty + j * 8;
        size_t dst = (((size_t)n * HALO + (h + 1)) * HALO + (wt * 32 + wl + 1)) * C_IN
                   + ct * 32 + tx;
        g_xb[dst] = __float2bfloat16(tile[tx][wl]);
    }
}

// ---------------------------------------------------------------------------
// Kernel 2: sign(W) OIHW -> mma.m16n8k16 B-fragment order (bf16)
// ---------------------------------------------------------------------------
__global__ void pack_w_kernel(const float* __restrict__ w) {
    int g = blockIdx.x * 256 + threadIdx.x;
    if (g >= 36 * 4 * 16 * 32) return;
    int lane  = g & 31;
    int nt    = (g >> 5) & 15;   // global n-tile (8 couts)
    int kt    = (g >> 9) & 3;    // k-tile (16 ci) within 64-chunk
    int chunk = g >> 11;         // 0..35: (ky,kx,cc)
    int ky = chunk / 12, kx = (chunk / 4) % 3, cc = chunk & 3;

    int ci0 = cc * 64 + kt * 16 + (lane & 3) * 2;
    int co  = nt * 8 + (lane >> 2);

    auto widx = [&](int ci) { return (((size_t)co * C_IN + ci) * 3 + ky) * 3 + kx; };
    uint32_t lo = (uint32_t)f2bf_bits(sgnf(w[widx(ci0)]))
                | ((uint32_t)f2bf_bits(sgnf(w[widx(ci0 + 1)])) << 16);
    uint32_t hi = (uint32_t)f2bf_bits(sgnf(w[widx(ci0 + 8)]))
                | ((uint32_t)f2bf_bits(sgnf(w[widx(ci0 + 9)])) << 16);
    g_wfrag[g] = make_uint2(lo, hi);
}

// ---------------------------------------------------------------------------
// Kernel 3: alpha[co] = mean |W[co,:,:,:]|
// ---------------------------------------------------------------------------
__global__ void alpha_kernel(const float* __restrict__ w) {
    __shared__ float red[256];
    int co = blockIdx.x;
    float s = 0.f;
    for (int i = threadIdx.x; i < 2304; i += 256)
        s += fabsf(w[(size_t)co * 2304 + i]);
    red[threadIdx.x] = s;
    __syncthreads();
    for (int o = 128; o > 0; o >>= 1) {
        if (threadIdx.x < o) red[threadIdx.x] += red[threadIdx.x + o];
        __syncthreads();
    }
    if (threadIdx.x == 0) g_alpha[co] = red[0] / 2304.f;
}

// ---------------------------------------------------------------------------
// Kernel 4: bf16 implicit-GEMM conv. CTA = TWO output rows (n, 2*h2+{0,1}):
//   M=256 pixels, N=128 couts, K = 36 chunks x 64 ci.
//   3-stage cp.async ring, ONE __syncthreads per chunk, warp tile 64x64.
// ---------------------------------------------------------------------------
#define A_PAD_HALVES 72          // 64 ci + 8 pad -> 144B row stride (ldmatrix conflict-free)
#define M_TILE 256
#define ASZ (M_TILE * A_PAD_HALVES * 2)   // 36864
#define BSZ (4 * 16 * 32 * 8)             // 16384
#define STAGE (ASZ + BSZ)                 // 53248
#define STAGES 3
#define SMEM_DYN (STAGES * STAGE)         // 159744

__device__ __forceinline__ void issue_loads(char* smem, int stage, int tid,
                                            int n, int h0, int it) {
    int ky = it / 12, kx = (it / 4) % 3, cc = it & 3;
    char* sA = smem + stage * STAGE;
    char* sB = sA + ASZ;
    // A: 2048 16B units; row r (0..255): h = h0 + (r>>7), pixel p = r&127
    const __nv_bfloat16* gx0 =
        &g_xb[(((size_t)n * HALO + h0 + ky) * HALO + kx) * C_IN + cc * 64];
#pragma unroll
    for (int v = 0; v < 8; v++) {
        int u = tid + v * 256;
        int row = u >> 3, seg = u & 7;
        int p = row & 127;
        uint32_t sa = (uint32_t)__cvta_generic_to_shared(sA + row * 144 + seg * 16);
        const void* ga = gx0 + ((size_t)(row >> 7) * HALO + p) * C_IN + seg * 8;
        asm volatile("cp.async.cg.shared.global [%0], [%1], 16;\n" :: "r"(sa), "l"(ga));
    }
    const char* gw = ((const char*)g_wfrag) + (size_t)it * BSZ;
#pragma unroll
    for (int v = 0; v < 4; v++) {
        int u = tid + v * 256;            // 1024 units of 16B for B
        uint32_t sa = (uint32_t)__cvta_generic_to_shared(sB + u * 16);
        asm volatile("cp.async.cg.shared.global [%0], [%1], 16;\n" :: "r"(sa), "l"(gw + u * 16));
    }
    asm volatile("cp.async.commit_group;\n");
}

__global__ void __launch_bounds__(256, 1) conv_kernel(float* __restrict__ out) {
    extern __shared__ char smem[];
    int tid = threadIdx.x;
    int lane = tid & 31, wid = tid >> 5;
    int wm = wid >> 1;        // 0..3 : 64-row M slab (wm 0,1 -> h0; 2,3 -> h1)
    int wn = wid & 1;         // 0..1 : 64-col N slab
    int h0 = blockIdx.x * 2, n = blockIdx.y;

    float acc[4][8][4];
#pragma unroll
    for (int a = 0; a < 4; a++)
#pragma unroll
        for (int b = 0; b < 8; b++)
#pragma unroll
            for (int c = 0; c < 4; c++) acc[a][b][c] = 0.f;

    issue_loads(smem, 0, tid, n, h0, 0);
    issue_loads(smem, 1, tid, n, h0, 1);

    int rl  = lane & 15;            // ldmatrix row-within-16
    int cl2 = (lane >> 4) * 8;      // ldmatrix col half-select

    for (int it = 0; it < 36; it++) {
        asm volatile("cp.async.wait_group 1;\n");
        __syncthreads();

        const char*  sA = smem + (it % 3) * STAGE;
        const uint2* sB = (const uint2*)(sA + ASZ);

#pragma unroll
        for (int kt = 0; kt < 4; kt++) {
            uint32_t a[4][4];
#pragma unroll
            for (int mt = 0; mt < 4; mt++) {
                uint32_t addr = (uint32_t)__cvta_generic_to_shared(
                    sA + ((wm * 64 + mt * 16 + rl) * A_PAD_HALVES + kt * 16 + cl2) * 2);
                asm volatile(
                    "ldmatrix.sync.aligned.m8n8.x4.shared.b16 {%0,%1,%2,%3}, [%4];"
                    : "=r"(a[mt][0]), "=r"(a[mt][1]), "=r"(a[mt][2]), "=r"(a[mt][3])
                    : "r"(addr));
            }
#pragma unroll
            for (int nt = 0; nt < 8; nt++) {
                uint2 t = sB[(kt * 16 + wn * 8 + nt) * 32 + lane];
#pragma unroll
                for (int mt = 0; mt < 4; mt++)
                    asm volatile(
                        "mma.sync.aligned.m16n8k16.row.col.f32.bf16.bf16.f32 "
                        "{%0,%1,%2,%3}, {%4,%5,%6,%7}, {%8,%9}, {%0,%1,%2,%3};"
                        : "+f"(acc[mt][nt][0]), "+f"(acc[mt][nt][1]),
                          "+f"(acc[mt][nt][2]), "+f"(acc[mt][nt][3])
                        : "r"(a[mt][0]), "r"(a[mt][1]), "r"(a[mt][2]), "r"(a[mt][3]),
                          "r"(t.x), "r"(t.y));
            }
        }

        if (it + 2 < 36)
            issue_loads(smem, (it + 2) % 3, tid, n, h0, it + 2);
        else
            asm volatile("cp.async.commit_group;\n");   // keep wait_group accounting
    }

    // Epilogue, two passes (one output row each), reusing ring smem.
    float* so = (float*)smem;
    int w = tid & 127;
    float al = g_alpha[w];
#pragma unroll
    for (int p = 0; p < 2; p++) {
        __syncthreads();
        if ((wm >> 1) == p) {
#pragma unroll
            for (int mt = 0; mt < 4; mt++) {
                int r0 = (wm & 1) * 64 + mt * 16 + (lane >> 2);   // w index
#pragma unroll
                for (int nt = 0; nt < 8; nt++) {
                    int c0 = wn * 64 + nt * 8 + (lane & 3) * 2;   // co index
                    so[(size_t)c0 * 132 + r0]           = acc[mt][nt][0];
                    so[(size_t)(c0 + 1) * 132 + r0]     = acc[mt][nt][1];
                    so[(size_t)c0 * 132 + r0 + 8]       = acc[mt][nt][2];
                    so[(size_t)(c0 + 1) * 132 + r0 + 8] = acc[mt][nt][3];
                }
            }
        }
        __syncthreads();
        float* ob = out + ((size_t)n * C_OUT * HW + (size_t)(h0 + p)) * HW;
#pragma unroll 4
        for (int k = 0; k < 64; k++) {
            int co = (tid >> 7) + k * 2;
            ob[(size_t)co * HW * HW + w] = so[(size_t)co * 132 + w] * al;
        }
    }
}

// ---------------------------------------------------------------------------
extern "C" void kernel_launch(void* const* d_in, const int* in_sizes, int n_in,
                              void* d_out, int out_size) {
    (void)in_sizes; (void)n_in; (void)out_size;
    const float* x = (const float*)d_in[0];
    const float* w = (const float*)d_in[1];
    float* out = (float*)d_out;

    cudaFuncSetAttribute(conv_kernel,
                         cudaFuncAttributeMaxDynamicSharedMemorySize, SMEM_DYN);

    dim3 pg(8, 4, N_IMG * HW);
    dim3 pb(32, 8);
    pack_x_kernel<<<pg, pb>>>(x);
    pack_w_kernel<<<288, 256>>>(w);
    alpha_kernel<<<C_OUT, 256>>>(w);
    conv_kernel<<<dim3(HW / 2, N_IMG), 256, SMEM_DYN>>>(out);
}

// round 7
// speedup vs baseline: 1.1932x; 1.0821x over previous
#include <cuda_runtime.h>
#include <cuda_fp16.h>
#include <cstdint>

#define N_IMG 16
#define C_IN  256
#define HW    128
#define C_OUT 128
#define HALO  130

// Scratch (module-load allocated; zero-initialized => halo stays zero forever)
__device__ __align__(1024) __half g_xb[(size_t)N_IMG * HALO * HALO * C_IN];
__device__ __align__(16) uint2 g_wfrag[36 * 4 * 16 * 32];   // [chunk][kt][ntile][lane]
__device__ float g_alpha[C_OUT];

__device__ __forceinline__ float sgnf(float v) {
    return (v > 0.f) ? 1.f : ((v < 0.f) ? -1.f : 0.f);
}
__device__ __forceinline__ uint16_t sgn_h(float v) {   // f16 bits of sign()
    return (v > 0.f) ? 0x3C00u : ((v < 0.f) ? 0xBC00u : 0u);
}

// ---------------------------------------------------------------------------
// Kernel 1: sign(x) NCHW f32 -> NHWC f16 with +1 halo offset (zero padding)
// ---------------------------------------------------------------------------
__global__ void pack_x_kernel(const float* __restrict__ x) {
    __shared__ float tile[32][33];
    int nh = blockIdx.z;              // n*128 + h
    int n = nh >> 7, h = nh & 127;
    int wt = blockIdx.y;              // 0..3  (w tile of 32)
    int ct = blockIdx.x;              // 0..7  (c tile of 32)
    int tx = threadIdx.x, ty = threadIdx.y;

#pragma unroll
    for (int j = 0; j < 4; j++) {
        int cl = ty + j * 8;
        float v = x[(((size_t)(n * C_IN + ct * 32 + cl)) * HW + h) * HW + wt * 32 + tx];
        tile[cl][tx] = sgnf(v);
    }
    __syncthreads();
#pragma unroll
    for (int j = 0; j < 4; j++) {
        int wl = ty + j * 8;
        size_t dst = (((size_t)n * HALO + (h + 1)) * HALO + (wt * 32 + wl + 1)) * C_IN
                   + ct * 32 + tx;
        g_xb[dst] = __float2half(tile[tx][wl]);
    }
}

// ---------------------------------------------------------------------------
// Kernel 2: sign(W) OIHW -> mma.m16n8k16 B-fragment order (f16)
// ---------------------------------------------------------------------------
__global__ void pack_w_kernel(const float* __restrict__ w) {
    int g = blockIdx.x * 256 + threadIdx.x;
    if (g >= 36 * 4 * 16 * 32) return;
    int lane  = g & 31;
    int nt    = (g >> 5) & 15;   // global n-tile (8 couts)
    int kt    = (g >> 9) & 3;    // k-tile (16 ci) within 64-chunk
    int chunk = g >> 11;         // 0..35: (ky,kx,cc)
    int ky = chunk / 12, kx = (chunk / 4) % 3, cc = chunk & 3;

    int ci0 = cc * 64 + kt * 16 + (lane & 3) * 2;
    int co  = nt * 8 + (lane >> 2);

    auto widx = [&](int ci) { return (((size_t)co * C_IN + ci) * 3 + ky) * 3 + kx; };
    uint32_t lo = (uint32_t)sgn_h(w[widx(ci0)])
                | ((uint32_t)sgn_h(w[widx(ci0 + 1)]) << 16);
    uint32_t hi = (uint32_t)sgn_h(w[widx(ci0 + 8)])
                | ((uint32_t)sgn_h(w[widx(ci0 + 9)]) << 16);
    g_wfrag[g] = make_uint2(lo, hi);
}

// ---------------------------------------------------------------------------
// Kernel 3: alpha[co] = mean |W[co,:,:,:]|
// ---------------------------------------------------------------------------
__global__ void alpha_kernel(const float* __restrict__ w) {
    __shared__ float red[256];
    int co = blockIdx.x;
    float s = 0.f;
    for (int i = threadIdx.x; i < 2304; i += 256)
        s += fabsf(w[(size_t)co * 2304 + i]);
    red[threadIdx.x] = s;
    __syncthreads();
    for (int o = 128; o > 0; o >>= 1) {
        if (threadIdx.x < o) red[threadIdx.x] += red[threadIdx.x + o];
        __syncthreads();
    }
    if (threadIdx.x == 0) g_alpha[co] = red[0] / 2304.f;
}

// ---------------------------------------------------------------------------
// Kernel 4: f16 implicit-GEMM conv. CTA = one output row (n,h):
//   M=128 pixels, N=128 couts, K = 36 chunks x 64 ci.
//   A-only 5-stage cp.async ring (B lives in registers, loaded from gmem),
//   ONE __syncthreads per chunk, 2 CTAs/SM.
// ---------------------------------------------------------------------------
#define A_PAD_HALVES 72          // 64 ci + 8 pad -> 144B row stride (ldmatrix conflict-free)
#define ASZ (128 * A_PAD_HALVES * 2)   // 18432
#define STAGES 5
#define SMEM_DYN (STAGES * ASZ)        // 92160

__device__ __forceinline__ void issue_A(char* smem, int stage, int tid,
                                        int n, int h, int it) {
    int ky = it / 12, kx = (it / 4) % 3, cc = it & 3;
    char* sA = smem + stage * ASZ;
    const __half* gx =
        &g_xb[(((size_t)n * HALO + h + ky) * HALO + kx) * C_IN + cc * 64];
#pragma unroll
    for (int v = 0; v < 4; v++) {
        int u = tid + v * 256;            // 1024 units of 16B
        int row = u >> 3, seg = u & 7;
        uint32_t sa = (uint32_t)__cvta_generic_to_shared(sA + row * 144 + seg * 16);
        const void* ga = gx + (size_t)row * C_IN + seg * 8;
        asm volatile("cp.async.cg.shared.global [%0], [%1], 16;\n" :: "r"(sa), "l"(ga));
    }
    asm volatile("cp.async.commit_group;\n");
}

__global__ void __launch_bounds__(256, 2) conv_kernel(float* __restrict__ out) {
    extern __shared__ char smem[];
    int tid = threadIdx.x;
    int lane = tid & 31, wid = tid >> 5;
    int wm = wid >> 2;        // 0..1 : 64-row M slab
    int wn = wid & 3;         // 0..3 : 32-col N slab
    int h = blockIdx.x, n = blockIdx.y;

    uint32_t acc[4][4][2];    // f16x2 accumulators
#pragma unroll
    for (int a = 0; a < 4; a++)
#pragma unroll
        for (int b = 0; b < 4; b++) { acc[a][b][0] = 0u; acc[a][b][1] = 0u; }

    // B fragments for the current chunk, straight from gmem (L2-resident)
    uint2 bfr[4][4];          // [kt][nt]
    const uint2* gB = g_wfrag + (size_t)(wn * 4) * 32 + lane;
#pragma unroll
    for (int kt = 0; kt < 4; kt++)
#pragma unroll
        for (int nt = 0; nt < 4; nt++)
            bfr[kt][nt] = gB[(kt * 16 + nt) * 32];

    issue_A(smem, 0, tid, n, h, 0);
    issue_A(smem, 1, tid, n, h, 1);
    issue_A(smem, 2, tid, n, h, 2);
    issue_A(smem, 3, tid, n, h, 3);

    int rl  = lane & 15;            // ldmatrix row-within-16
    int cl2 = (lane >> 4) * 8;      // ldmatrix col half-select

    for (int it = 0; it < 36; it++) {
        asm volatile("cp.async.wait_group 3;\n");
        __syncthreads();

        const char* sA = smem + (it % 5) * ASZ;

#pragma unroll
        for (int kt = 0; kt < 4; kt++) {
            uint32_t a[4][4];
#pragma unroll
            for (int mt = 0; mt < 4; mt++) {
                uint32_t addr = (uint32_t)__cvta_generic_to_shared(
                    sA + ((wm * 64 + mt * 16 + rl) * A_PAD_HALVES + kt * 16 + cl2) * 2);
                asm volatile(
                    "ldmatrix.sync.aligned.m8n8.x4.shared.b16 {%0,%1,%2,%3}, [%4];"
                    : "=r"(a[mt][0]), "=r"(a[mt][1]), "=r"(a[mt][2]), "=r"(a[mt][3])
                    : "r"(addr));
            }
#pragma unroll
            for (int mt = 0; mt < 4; mt++)
#pragma unroll
                for (int nt = 0; nt < 4; nt++)
                    asm volatile(
                        "mma.sync.aligned.m16n8k16.row.col.f16.f16.f16.f16 "
                        "{%0,%1}, {%2,%3,%4,%5}, {%6,%7}, {%0,%1};"
                        : "+r"(acc[mt][nt][0]), "+r"(acc[mt][nt][1])
                        : "r"(a[mt][0]), "r"(a[mt][1]), "r"(a[mt][2]), "r"(a[mt][3]),
                          "r"(bfr[kt][nt].x), "r"(bfr[kt][nt].y));
        }

        // Prefetch next chunk's B fragments into registers (hidden under
        // next chunk's barrier + ldmatrix head).
        if (it + 1 < 36) {
            const uint2* gBn = g_wfrag + (size_t)(it + 1) * 2048
                             + (size_t)(wn * 4) * 32 + lane;
#pragma unroll
            for (int kt = 0; kt < 4; kt++)
#pragma unroll
                for (int nt = 0; nt < 4; nt++)
                    bfr[kt][nt] = gBn[(kt * 16 + nt) * 32];
        }

        // Issue A for chunk it+4 into stage (it+4)%5 == (it-1)%5: that stage
        // was consumed at it-1 and every warp passed this iter's barrier.
        if (it + 4 < 36)
            issue_A(smem, (it + 4) % 5, tid, n, h, it + 4);
        else
            asm volatile("cp.async.commit_group;\n");   // keep wait_group accounting
    }

    // Epilogue: f16 acc -> smem [co][w] (pad 132) as f32, then coalesced
    // NCHW store with alpha[w] (reference broadcasts alpha along width axis)
    __syncthreads();
    float* so = (float*)smem;
#pragma unroll
    for (int mt = 0; mt < 4; mt++) {
        int r0 = wm * 64 + mt * 16 + (lane >> 2);   // w index
#pragma unroll
        for (int nt = 0; nt < 4; nt++) {
            int c0 = wn * 32 + nt * 8 + (lane & 3) * 2;   // co index
            float2 f0 = __half22float2(*reinterpret_cast<__half2*>(&acc[mt][nt][0]));
            float2 f1 = __half22float2(*reinterpret_cast<__half2*>(&acc[mt][nt][1]));
            so[(size_t)c0 * 132 + r0]           = f0.x;
            so[(size_t)(c0 + 1) * 132 + r0]     = f0.y;
            so[(size_t)c0 * 132 + r0 + 8]       = f1.x;
            so[(size_t)(c0 + 1) * 132 + r0 + 8] = f1.y;
        }
    }
    __syncthreads();

    int w = tid & 127;
    float al = g_alpha[w];
    float* ob = out + ((size_t)n * C_OUT * HW + (size_t)h) * HW;   // + co*HW*HW + w
#pragma unroll 4
    for (int k = 0; k < 64; k++) {
        int co = (tid >> 7) + k * 2;
        ob[(size_t)co * HW * HW + w] = so[(size_t)co * 132 + w] * al;
    }
}

// ---------------------------------------------------------------------------
extern "C" void kernel_launch(void* const* d_in, const int* in_sizes, int n_in,
                              void* d_out, int out_size) {
    (void)in_sizes; (void)n_in; (void)out_size;
    const float* x = (const float*)d_in[0];
    const float* w = (const float*)d_in[1];
    float* out = (float*)d_out;

    cudaFuncSetAttribute(conv_kernel,
                         cudaFuncAttributeMaxDynamicSharedMemorySize, SMEM_DYN);

    dim3 pg(8, 4, N_IMG * HW);
    dim3 pb(32, 8);
    pack_x_kernel<<<pg, pb>>>(x);
    pack_w_kernel<<<288, 256>>>(w);
    alpha_kernel<<<C_OUT, 256>>>(w);
    conv_kernel<<<dim3(HW, N_IMG), 256, SMEM_DYN>>>(out);
}

// round 8
// speedup vs baseline: 1.3530x; 1.1339x over previous
#include <cuda_runtime.h>
#include <cuda_fp16.h>
#include <cstdint>

#define N_IMG 16
#define C_IN  256
#define HW    128
#define C_OUT 128
#define HALO  130

// Scratch (module-load allocated; zero-initialized => halo stays zero forever)
__device__ __align__(1024) __half g_xb[(size_t)N_IMG * HALO * HALO * C_IN];
__device__ __align__(16) uint2 g_wfrag[36 * 4 * 16 * 32];   // [chunk][kt][ntile][lane]
__device__ float g_alpha[C_OUT];

__device__ __forceinline__ float sgnf(float v) {
    return (v > 0.f) ? 1.f : ((v < 0.f) ? -1.f : 0.f);
}
__device__ __forceinline__ uint16_t sgn_h(float v) {   // f16 bits of sign()
    return (v > 0.f) ? 0x3C00u : ((v < 0.f) ? 0xBC00u : 0u);
}

// ---------------------------------------------------------------------------
// Kernel 1: sign(x) NCHW f32 -> NHWC f16 with +1 halo offset (zero padding)
// 64c x 32w tiles; __half2 stores -> fully coalesced 128B write transactions.
// ---------------------------------------------------------------------------
__global__ void pack_x_kernel(const float* __restrict__ x) {
    __shared__ float tile[64][33];
    int nh = blockIdx.z;              // n*128 + h
    int n = nh >> 7, h = nh & 127;
    int wt = blockIdx.y;              // 0..3  (w tile of 32)
    int ct = blockIdx.x;              // 0..3  (c tile of 64)
    int tx = threadIdx.x, ty = threadIdx.y;

#pragma unroll
    for (int j = 0; j < 8; j++) {
        int cl = ty + j * 8;          // 0..63
        float v = x[(((size_t)(n * C_IN + ct * 64 + cl)) * HW + h) * HW + wt * 32 + tx];
        tile[cl][tx] = sgnf(v);
    }
    __syncthreads();
#pragma unroll
    for (int j = 0; j < 4; j++) {
        int wl = ty + j * 8;          // 0..31
        __half2 hv = __floats2half2_rn(tile[tx * 2][wl], tile[tx * 2 + 1][wl]);
        size_t dsth2 = ((((size_t)n * HALO + (h + 1)) * HALO + (wt * 32 + wl + 1)) * C_IN
                        + ct * 64) >> 1;
        reinterpret_cast<__half2*>(g_xb)[dsth2 + tx] = hv;
    }
}

// ---------------------------------------------------------------------------
// Kernel 2: sign(W) OIHW -> mma.m16n8k16 B-fragment order (f16)
// chunk = ky*12 + kx*4 + cc
// ---------------------------------------------------------------------------
__global__ void pack_w_kernel(const float* __restrict__ w) {
    int g = blockIdx.x * 256 + threadIdx.x;
    if (g >= 36 * 4 * 16 * 32) return;
    int lane  = g & 31;
    int nt    = (g >> 5) & 15;   // global n-tile (8 couts)
    int kt    = (g >> 9) & 3;    // k-tile (16 ci) within 64-chunk
    int chunk = g >> 11;         // 0..35: (ky,kx,cc)
    int ky = chunk / 12, kx = (chunk / 4) % 3, cc = chunk & 3;

    int ci0 = cc * 64 + kt * 16 + (lane & 3) * 2;
    int co  = nt * 8 + (lane >> 2);

    auto widx = [&](int ci) { return (((size_t)co * C_IN + ci) * 3 + ky) * 3 + kx; };
    uint32_t lo = (uint32_t)sgn_h(w[widx(ci0)])
                | ((uint32_t)sgn_h(w[widx(ci0 + 1)]) << 16);
    uint32_t hi = (uint32_t)sgn_h(w[widx(ci0 + 8)])
                | ((uint32_t)sgn_h(w[widx(ci0 + 9)]) << 16);
    g_wfrag[g] = make_uint2(lo, hi);
}

// ---------------------------------------------------------------------------
// Kernel 3: alpha[co] = mean |W[co,:,:,:]|
// ---------------------------------------------------------------------------
__global__ void alpha_kernel(const float* __restrict__ w) {
    __shared__ float red[256];
    int co = blockIdx.x;
    float s = 0.f;
    for (int i = threadIdx.x; i < 2304; i += 256)
        s += fabsf(w[(size_t)co * 2304 + i]);
    red[threadIdx.x] = s;
    __syncthreads();
    for (int o = 128; o > 0; o >>= 1) {
        if (threadIdx.x < o) red[threadIdx.x] += red[threadIdx.x + o];
        __syncthreads();
    }
    if (threadIdx.x == 0) g_alpha[co] = red[0] / 2304.f;
}

// ---------------------------------------------------------------------------
// Kernel 4: f16 implicit-GEMM conv. CTA = one output row (n,h).
//   M=128, N=128, K = 12 A-stages (ky,cc) x 3 kx x 64 ci.
//   A tile = 130 pixels x 64 ci, reused by all 3 kx via +kx*144B address shift.
//   5-stage A ring, ONE __syncthreads per A-stage (12 total), B in registers.
// ---------------------------------------------------------------------------
#define A_PAD_HALVES 72          // 64 ci + 8 pad -> 144B row stride
#define A_ROWS 130
#define ASZ (A_ROWS * A_PAD_HALVES * 2)   // 18720
#define STAGES 5
#define SMEM_DYN (STAGES * ASZ)           // 93600

__device__ __forceinline__ void issue_A(char* smem, int stage, int tid,
                                        int n, int h, int s) {
    int ky = s >> 2, cc = s & 3;
    char* sA = smem + stage * ASZ;
    const __half* gx = &g_xb[(((size_t)n * HALO + h + ky) * HALO) * C_IN + cc * 64];
#pragma unroll
    for (int v = 0; v < 5; v++) {
        int u = tid + v * 256;            // 1040 units of 16B (130 rows x 8)
        if (u < A_ROWS * 8) {
            int row = u >> 3, seg = u & 7;
            uint32_t sa = (uint32_t)__cvta_generic_to_shared(sA + row * 144 + seg * 16);
            const void* ga = gx + (size_t)row * C_IN + seg * 8;
            asm volatile("cp.async.cg.shared.global [%0], [%1], 16;\n" :: "r"(sa), "l"(ga));
        }
    }
    asm volatile("cp.async.commit_group;\n");
}

__global__ void __launch_bounds__(256, 2) conv_kernel(float* __restrict__ out) {
    extern __shared__ char smem[];
    int tid = threadIdx.x;
    int lane = tid & 31, wid = tid >> 5;
    int wm = wid >> 2;        // 0..1 : 64-row M slab
    int wn = wid & 3;         // 0..3 : 32-col N slab
    int h = blockIdx.x, n = blockIdx.y;

    uint32_t acc[4][4][2];    // f16x2 accumulators
#pragma unroll
    for (int a = 0; a < 4; a++)
#pragma unroll
        for (int b = 0; b < 4; b++) { acc[a][b][0] = 0u; acc[a][b][1] = 0u; }

    // B fragments for step 0 (chunk 0 = ky0,kx0,cc0), straight from gmem
    uint2 bfr[4][4];          // [kt][nt]
    {
        const uint2* gB = g_wfrag + (size_t)(wn * 4) * 32 + lane;
#pragma unroll
        for (int kt = 0; kt < 4; kt++)
#pragma unroll
            for (int nt = 0; nt < 4; nt++)
                bfr[kt][nt] = gB[(kt * 16 + nt) * 32];
    }

    issue_A(smem, 0, tid, n, h, 0);
    issue_A(smem, 1, tid, n, h, 1);
    issue_A(smem, 2, tid, n, h, 2);
    issue_A(smem, 3, tid, n, h, 3);

    int rl  = lane & 15;            // ldmatrix row-within-16
    int cl2 = (lane >> 4) * 8;      // ldmatrix col half-select

    for (int s = 0; s < 12; s++) {
        asm volatile("cp.async.wait_group 3;\n");
        __syncthreads();

        const char* sA = smem + (s % 5) * ASZ;

        // Refill ring: stage (s+4)%5 == (s-1)%5, consumed at s-1; every warp
        // passed this iteration's barrier, so the overwrite is safe.
        if (s + 4 < 12)
            issue_A(smem, (s + 4) % 5, tid, n, h, s + 4);
        else
            asm volatile("cp.async.commit_group;\n");   // keep wait_group accounting

#pragma unroll
        for (int kx = 0; kx < 3; kx++) {
#pragma unroll
            for (int kt = 0; kt < 4; kt++) {
                uint32_t a[4][4];
#pragma unroll
                for (int mt = 0; mt < 4; mt++) {
                    uint32_t addr = (uint32_t)__cvta_generic_to_shared(
                        sA + ((wm * 64 + mt * 16 + rl + kx) * A_PAD_HALVES
                              + kt * 16 + cl2) * 2);
                    asm volatile(
                        "ldmatrix.sync.aligned.m8n8.x4.shared.b16 {%0,%1,%2,%3}, [%4];"
                        : "=r"(a[mt][0]), "=r"(a[mt][1]), "=r"(a[mt][2]), "=r"(a[mt][3])
                        : "r"(addr));
                }
#pragma unroll
                for (int mt = 0; mt < 4; mt++)
#pragma unroll
                    for (int nt = 0; nt < 4; nt++)
                        asm volatile(
                            "mma.sync.aligned.m16n8k16.row.col.f16.f16.f16.f16 "
                            "{%0,%1}, {%2,%3,%4,%5}, {%6,%7}, {%0,%1};"
                            : "+r"(acc[mt][nt][0]), "+r"(acc[mt][nt][1])
                            : "r"(a[mt][0]), "r"(a[mt][1]), "r"(a[mt][2]), "r"(a[mt][3]),
                              "r"(bfr[kt][nt].x), "r"(bfr[kt][nt].y));
            }

            // Prefetch B for the next (s,kx) step; ~64 MMAs of lead time.
            int step = s * 3 + kx + 1;
            if (step < 36) {
                int s2  = (kx < 2) ? s : s + 1;
                int kx2 = (kx < 2) ? kx + 1 : 0;
                int chunk2 = (s2 >> 2) * 12 + kx2 * 4 + (s2 & 3);
                const uint2* gBn = g_wfrag + (size_t)chunk2 * 2048
                                 + (size_t)(wn * 4) * 32 + lane;
#pragma unroll
                for (int kt = 0; kt < 4; kt++)
#pragma unroll
                    for (int nt = 0; nt < 4; nt++)
                        bfr[kt][nt] = gBn[(kt * 16 + nt) * 32];
            }
        }
    }

    // Epilogue: f16 acc -> smem [co][w] (pad 132) as f32, then coalesced
    // NCHW store with alpha[w] (reference broadcasts alpha along width axis)
    __syncthreads();
    float* so = (float*)smem;
#pragma unroll
    for (int mt = 0; mt < 4; mt++) {
        int r0 = wm * 64 + mt * 16 + (lane >> 2);   // w index
#pragma unroll
        for (int nt = 0; nt < 4; nt++) {
            int c0 = wn * 32 + nt * 8 + (lane & 3) * 2;   // co index
            float2 f0 = __half22float2(*reinterpret_cast<__half2*>(&acc[mt][nt][0]));
            float2 f1 = __half22float2(*reinterpret_cast<__half2*>(&acc[mt][nt][1]));
            so[(size_t)c0 * 132 + r0]           = f0.x;
            so[(size_t)(c0 + 1) * 132 + r0]     = f0.y;
            so[(size_t)c0 * 132 + r0 + 8]       = f1.x;
            so[(size_t)(c0 + 1) * 132 + r0 + 8] = f1.y;
        }
    }
    __syncthreads();

    int w = tid & 127;
    float al = g_alpha[w];
    float* ob = out + ((size_t)n * C_OUT * HW + (size_t)h) * HW;   // + co*HW*HW + w
#pragma unroll 4
    for (int k = 0; k < 64; k++) {
        int co = (tid >> 7) + k * 2;
        ob[(size_t)co * HW * HW + w] = so[(size_t)co * 132 + w] * al;
    }
}

// ---------------------------------------------------------------------------
extern "C" void kernel_launch(void* const* d_in, const int* in_sizes, int n_in,
                              void* d_out, int out_size) {
    (void)in_sizes; (void)n_in; (void)out_size;
    const float* x = (const float*)d_in[0];
    const float* w = (const float*)d_in[1];
    float* out = (float*)d_out;

    cudaFuncSetAttribute(conv_kernel,
                         cudaFuncAttributeMaxDynamicSharedMemorySize, SMEM_DYN);

    dim3 pg(4, 4, N_IMG * HW);
    dim3 pb(32, 8);
    pack_x_kernel<<<pg, pb>>>(x);
    pack_w_kernel<<<288, 256>>>(w);
    alpha_kernel<<<C_OUT, 256>>>(w);
    conv_kernel<<<dim3(HW, N_IMG), 256, SMEM_DYN>>>(out);
}